// round 12
// baseline (speedup 1.0000x reference)
#include <cuda_runtime.h>
#include <cuda_fp16.h>
#include <cstdint>

// AlignedLinear: y[n, o*9+d] = alpha * sum_i x[n, i*9+d] * K[r(d), i, o]
// r(d)=0 d=0; 1 d=1..3; 2 d=4..8.
//
// R12: fp16 m16n8k16 path (same 10-bit mantissa as tf32; fp32 accumulate).
// X staged into smem as k-paired fp16x2 words: word[k2*9+d] = (x[9(2k2)+d],
// x[9(2k2+1)+d]) — exactly the m16n8k16 A-fragment format, so A = 4 LDS.32
// per k16 fragment with affine conflict-free addressing (SROW=580 = 4 mod 32).
// Tile = 16 nodes * 580 words * 4B = 37120 B -> 5 CTAs/SM (occ 31%), no m16
// padding. Outputs packed fp16x2 into the same dead words (o-pairs mirror
// k-pairs); coalesced fp32 float4 epilogue. K pre-converted (alpha folded,
// RN fp16) to a fragment-major global buffer; B via coalesced LDG.64.

#define MT        16
#define DIMT      9
#define MUL       128
#define ROWF      1152
#define SROW      580              // smem row stride in fp16x2 words
#define PAIRS     576              // 64 k2 * 9 d
#define TILE_W    (MT * SROW)      // 9280 words = 37120 B
#define NTHREADS  128
#define ALPHA_F   0.08838834764831845f  // sqrt(1/128)

// kbuf[r][s(8)][nt(16)][lane(32)][j(2)] : fp16x2 b_j of fragment (s,nt), irrep r
#define KB_WORDS  (3 * 8 * 16 * 32 * 2)
__device__ __align__(16) uint32_t g_kbuf[KB_WORDS];

static __device__ __forceinline__ uint32_t pack_f16x2(float lo, float hi) {
    uint32_t u;
    asm("cvt.rn.f16x2.f32 %0, %1, %2;" : "=r"(u) : "f"(hi), "f"(lo));
    return u;
}

static __device__ __forceinline__ void mma_f16(float c[4],
    uint32_t a0, uint32_t a1, uint32_t a2, uint32_t a3,
    uint32_t b0, uint32_t b1)
{
    asm volatile(
        "mma.sync.aligned.m16n8k16.row.col.f32.f16.f16.f32 "
        "{%0,%1,%2,%3}, {%4,%5,%6,%7}, {%8,%9}, {%0,%1,%2,%3};"
        : "+f"(c[0]), "+f"(c[1]), "+f"(c[2]), "+f"(c[3])
        : "r"(a0), "r"(a1), "r"(a2), "r"(a3), "r"(b0), "r"(b1));
}

static __device__ __forceinline__ uint32_t lds32(uint32_t a) {
    uint32_t v;
    asm volatile("ld.shared.b32 %0, [%1];" : "=r"(v) : "r"(a));
    return v;
}
static __device__ __forceinline__ void sts32(uint32_t a, uint32_t v) {
    asm volatile("st.shared.b32 [%0], %1;" :: "r"(a), "r"(v));
}

// ---- Prep: K[r][i][o] fp32 -> fragment-major fp16x2 (RN), alpha folded ----
__global__ void prep_k_kernel(const float* __restrict__ kern)
{
    int idx = blockIdx.x * blockDim.x + threadIdx.x;
    if (idx >= KB_WORDS) return;
    int j    = idx & 1;
    int lane = (idx >> 1) & 31;
    int nt   = (idx >> 6) & 15;
    int s    = (idx >> 10) & 7;
    int r    = idx >> 13;
    int k0 = s * 16 + 2 * (lane & 3) + 8 * j;   // b_j covers k0, k0+1
    int o  = nt * 8 + (lane >> 2);
    float v0 = ALPHA_F * kern[(r * MUL + k0    ) * MUL + o];
    float v1 = ALPHA_F * kern[(r * MUL + k0 + 1) * MUL + o];
    g_kbuf[idx] = pack_f16x2(v0, v1);
}

// One irrep group: mma all DC dims over 8 k16 steps, then pack fp16x2 outputs
// into the now-dead words (o2*9+d mirrors k2*9+d for this group's d range).
template<int R, int D0, int DC>
static __device__ __forceinline__ void process_group(
    uint32_t sbase, int g, int tg, int lane, int warp)
{
    const uint2* kb = reinterpret_cast<const uint2*>(g_kbuf)
                    + ((size_t)(R * 8) * 16 + warp * 4) * 32 + lane;
    const uint32_t pA = sbase + 4u * (uint32_t)(g * SROW + 9 * tg);

    float c[DC][4][4];
    #pragma unroll
    for (int dd = 0; dd < DC; ++dd)
        #pragma unroll
        for (int nt = 0; nt < 4; ++nt)
            #pragma unroll
            for (int i = 0; i < 4; ++i) c[dd][nt][i] = 0.f;

    uint2 bnxt[4];
    #pragma unroll
    for (int nt = 0; nt < 4; ++nt) bnxt[nt] = __ldg(kb + nt * 32);

    #pragma unroll
    for (int s = 0; s < 8; ++s) {
        uint2 cur[4];
        #pragma unroll
        for (int nt = 0; nt < 4; ++nt) cur[nt] = bnxt[nt];
        if (s < 7) {
            const uint2* kbn = kb + (s + 1) * 512;
            #pragma unroll
            for (int nt = 0; nt < 4; ++nt) bnxt[nt] = __ldg(kbn + nt * 32);
        }
        #pragma unroll
        for (int dd = 0; dd < DC; ++dd) {
            // word = (8s+tg)*9 + d = 72s + 9tg + d; +36 words for k2+4;
            // +8 rows = +8*SROW*4 = 18560 B.
            const uint32_t b0 = pA + 4u * (uint32_t)(72 * s + D0 + dd);
            uint32_t a0 = lds32(b0);
            uint32_t a1 = lds32(b0 + 18560u);
            uint32_t a2 = lds32(b0 + 144u);
            uint32_t a3 = lds32(b0 + 144u + 18560u);
            #pragma unroll
            for (int nt = 0; nt < 4; ++nt)
                mma_f16(c[dd][nt], a0, a1, a2, a3, cur[nt].x, cur[nt].y);
        }
    }

    __syncthreads();   // all warps done reading this group's d-words

    // word = (warp*16 + 4nt + tg)*9 + d  (o2 = o/2, o = warp*32+8nt+2tg)
    const uint32_t pW = sbase + 4u * (uint32_t)(g * SROW + (warp * 16 + tg) * 9);
    #pragma unroll
    for (int dd = 0; dd < DC; ++dd) {
        #pragma unroll
        for (int nt = 0; nt < 4; ++nt) {
            const uint32_t off = pW + 4u * (uint32_t)(36 * nt + D0 + dd);
            sts32(off,          pack_f16x2(c[dd][nt][0], c[dd][nt][1]));
            sts32(off + 18560u, pack_f16x2(c[dd][nt][2], c[dd][nt][3]));
        }
    }
}

__global__ void __launch_bounds__(NTHREADS, 5)
aligned_linear_f16(const float* __restrict__ x,
                   float* __restrict__ y,
                   int n_nodes)
{
    extern __shared__ uint32_t sX[];   // [MT][SROW] fp16x2 pair words
    const uint32_t sbase = (uint32_t)__cvta_generic_to_shared(sX);

    const int tid  = threadIdx.x;
    const int lane = tid & 31;
    const int warp = tid >> 5;
    const int g    = lane >> 2;
    const int tg   = lane & 3;

    const long long node0 = (long long)blockIdx.x * MT;

    // ---- Stage: LDG fp32 pairs (e, e+9) -> fp16x2 word k2*9+d ----
    #pragma unroll 4
    for (int it = tid; it < MT * PAIRS; it += NTHREADS) {
        int row = it / PAIRS;
        int p   = it - row * PAIRS;
        int k2  = p / 9;
        int d   = p - 9 * k2;
        long long n = node0 + row;
        float v0 = 0.f, v1 = 0.f;
        if (n < (long long)n_nodes) {
            const float* src = x + n * ROWF + k2 * 18 + d;
            v0 = src[0];
            v1 = src[9];
        }
        sX[row * SROW + p] = pack_f16x2(v0, v1);
    }
    __syncthreads();

    process_group<0, 0, 1>(sbase, g, tg, lane, warp);
    process_group<1, 1, 3>(sbase, g, tg, lane, warp);
    process_group<2, 4, 3>(sbase, g, tg, lane, warp);
    process_group<2, 7, 2>(sbase, g, tg, lane, warp);

    __syncthreads();   // all writebacks visible

    // ---- Epilogue: unpack fp16x2 pairs -> coalesced float4 fp32 stores ----
    #pragma unroll 4
    for (int it = tid; it < MT * (ROWF / 4); it += NTHREADS) {
        int row = it / (ROWF / 4);
        int c4  = it - row * (ROWF / 4);
        long long n = node0 + row;
        if (n >= (long long)n_nodes) continue;
        int e0 = c4 * 4;
        int k  = e0 / 9;
        int d  = e0 - 9 * k;
        const uint32_t rb = (uint32_t)(row * SROW);
        float o[4];
        #pragma unroll
        for (int j = 0; j < 4; ++j) {
            uint32_t pw = sX[rb + (uint32_t)((k >> 1) * 9 + d)];
            uint32_t h  = (k & 1) ? (pw >> 16) : (pw & 0xffffu);
            o[j] = __half2float(__ushort_as_half((unsigned short)h));
            if (++d == DIMT) { d = 0; ++k; }
        }
        *reinterpret_cast<float4*>(y + n * ROWF + e0) =
            make_float4(o[0], o[1], o[2], o[3]);
    }
}

extern "C" void kernel_launch(void* const* d_in, const int* in_sizes, int n_in,
                              void* d_out, int out_size)
{
    const float* x = (const float*)d_in[0];
    const float* k = (const float*)d_in[1];
    float* y = (float*)d_out;
    int n_nodes = in_sizes[0] / ROWF;

    prep_k_kernel<<<(KB_WORDS + 255) / 256, 256>>>(k);

    size_t smem_bytes = (size_t)TILE_W * sizeof(uint32_t);   // 37120 B
    cudaFuncSetAttribute(aligned_linear_f16,
                         cudaFuncAttributeMaxDynamicSharedMemorySize,
                         (int)smem_bytes);

    int grid = (n_nodes + MT - 1) / MT;
    aligned_linear_f16<<<grid, NTHREADS, smem_bytes>>>(x, y, n_nodes);
}

// round 13
// speedup vs baseline: 1.3852x; 1.3852x over previous
#include <cuda_runtime.h>
#include <cuda.h>
#include <cstdint>

// AlignedLinear: y[n, o*9+d] = alpha * sum_i x[n, i*9+d] * K[r(d), i, o]
// r(d)=0 d=0; 1 d=1..3; 2 d=4..8.
//
// R13: persistent double-buffered pipeline on the R11 compute core.
// 296 CTAs (2/SM), each owns TWO MT=12 tile buffers (SW128 TMA layout,
// view [32f][node][36seg], swizzle key=(node+4*seg)&7). Steady state:
// compute tile t in buf p while TMA-loading tile t+stride into buf q
// (issued mid-compute, after bulk.wait_group drains buf q's prior store).
// m16 fragment rows 12..15 are padding: A reads discarded, writeback
// predicated off (g<4). DC=5 irrep split 3+2. B fragments from
// fragment-major tf32 global buffer (alpha folded), prefetch depth 2.

#define MT        12
#define DIMT      9
#define MUL       128
#define ROWF      1152
#define TILE_BYTES (MT * ROWF * 4)      // 55296
#define SEG_STRIDE (MT * 128)           // 1536 B per seg in smem
#define NTHREADS  128
#define ALPHA_F   0.08838834764831845f  // sqrt(1/128)

#define KB_WORDS  (3 * 16 * 16 * 64)
__device__ __align__(16) uint32_t g_kbuf[KB_WORDS];

static __device__ __forceinline__ uint32_t f2tf32(float f) {
    uint32_t u;
    asm("cvt.rna.tf32.f32 %0, %1;" : "=r"(u) : "f"(f));
    return u;
}

static __device__ __forceinline__ void mma_tf32(float c[4],
    uint32_t a0, uint32_t a1, uint32_t a2, uint32_t a3,
    uint32_t b0, uint32_t b1)
{
    asm volatile(
        "mma.sync.aligned.m16n8k8.row.col.f32.tf32.tf32.f32 "
        "{%0,%1,%2,%3}, {%4,%5,%6,%7}, {%8,%9}, {%0,%1,%2,%3};"
        : "+f"(c[0]), "+f"(c[1]), "+f"(c[2]), "+f"(c[3])
        : "r"(a0), "r"(a1), "r"(a2), "r"(a3), "r"(b0), "r"(b1));
}

// ---- Prep: K[r][i][o] fp32 -> fragment-major tf32 (RNA), alpha folded ----
__global__ void prep_k_kernel(const float* __restrict__ kern)
{
    int idx = blockIdx.x * blockDim.x + threadIdx.x;
    if (idx >= KB_WORDS) return;
    int j    = idx & 1;
    int lane = (idx >> 1) & 31;
    int nt   = (idx >> 6) & 15;
    int k8   = (idx >> 10) & 15;
    int r    = idx >> 14;
    int k = k8 * 8 + (lane & 3) + 4 * j;
    int o = nt * 8 + (lane >> 2);
    g_kbuf[idx] = f2tf32(ALPHA_F * kern[(r * MUL + k) * MUL + o]);
}

// Swizzled byte offset (relative to node-row base) of word w = 9k+d.
// chunk = seg*MT + node; key = ((node + 4*seg)&7)<<4. Rows g and g+8 share
// the key; row g+8 is +1024 B.
static __device__ __forceinline__ uint32_t swz(int w, int g) {
    uint32_t s  = (uint32_t)w >> 5;
    uint32_t ky = (((uint32_t)g + 4u * s) & 7u) << 4;
    return s * (uint32_t)SEG_STRIDE + ((((uint32_t)w & 31u) << 2) ^ ky);
}

static __device__ __forceinline__ uint32_t lds32(uint32_t a) {
    uint32_t v;
    asm volatile("ld.shared.b32 %0, [%1];" : "=r"(v) : "r"(a));
    return v;
}
static __device__ __forceinline__ void sts32(uint32_t a, float v) {
    asm volatile("st.shared.b32 [%0], %1;" :: "r"(a), "f"(v));
}

static __device__ __forceinline__ void mbar_wait(uint32_t bar, uint32_t parity) {
    asm volatile(
        "{\n\t.reg .pred P;\n\t"
        "WL_%=:\n\t"
        "mbarrier.try_wait.parity.acquire.cta.shared::cta.b64 P, [%0], %1, 0x989680;\n\t"
        "@P bra WD_%=;\n\t"
        "bra WL_%=;\n\t"
        "WD_%=:\n\t}"
        :: "r"(bar), "r"(parity) : "memory");
}

template<int R, int D0, int DC>
static __device__ __forceinline__ void process_group(
    uint32_t tbase, int g, int tg, int lane, int warp)
{
    const uint2* kb = reinterpret_cast<const uint2*>(g_kbuf)
                    + ((size_t)R * 256 + warp * 4) * 32 + lane;
    const uint32_t rowb = tbase + (uint32_t)g * 128u;
    const bool hi_valid = (g < MT - 8);   // node g+8 exists (rows 12..15: pad)

    float c[DC][4][4];
    #pragma unroll
    for (int dd = 0; dd < DC; ++dd)
        #pragma unroll
        for (int nt = 0; nt < 4; ++nt)
            #pragma unroll
            for (int i = 0; i < 4; ++i) c[dd][nt][i] = 0.f;

    uint2 buf[2][4];
    #pragma unroll
    for (int nt = 0; nt < 4; ++nt) buf[0][nt] = __ldg(kb + nt * 32);
    #pragma unroll
    for (int nt = 0; nt < 4; ++nt) buf[1][nt] = __ldg(kb + 512 + nt * 32);

    #pragma unroll 2
    for (int k8 = 0; k8 < 16; ++k8) {
        uint2 cur[4];
        #pragma unroll
        for (int nt = 0; nt < 4; ++nt) cur[nt] = buf[k8 & 1][nt];
        if (k8 < 14) {
            const uint2* kbn = kb + (k8 + 2) * 512;
            #pragma unroll
            for (int nt = 0; nt < 4; ++nt)
                buf[k8 & 1][nt] = __ldg(kbn + nt * 32);
        }
        #pragma unroll
        for (int dd = 0; dd < DC; ++dd) {
            const int w0 = 72 * k8 + 9 * tg + (D0 + dd);
            const uint32_t o0 = rowb + swz(w0,      g);
            const uint32_t o1 = rowb + swz(w0 + 36, g);
            uint32_t a0 = lds32(o0);
            uint32_t a1 = lds32(o0 + 1024);   // pad rows: garbage, discarded
            uint32_t a2 = lds32(o1);
            uint32_t a3 = lds32(o1 + 1024);
            #pragma unroll
            for (int nt = 0; nt < 4; ++nt)
                mma_tf32(c[dd][nt], a0, a1, a2, a3, cur[nt].x, cur[nt].y);
        }
    }

    __syncthreads();   // all warps done reading this group's X words

    #pragma unroll
    for (int dd = 0; dd < DC; ++dd) {
        #pragma unroll
        for (int nt = 0; nt < 4; ++nt) {
            const int o = warp * 32 + nt * 8 + 2 * tg;
            const int w = o * 9 + (D0 + dd);
            const uint32_t p0 = rowb + swz(w,     g);
            const uint32_t p1 = rowb + swz(w + 9, g);
            sts32(p0, c[dd][nt][0]);
            sts32(p1, c[dd][nt][1]);
            if (hi_valid) {
                sts32(p0 + 1024, c[dd][nt][2]);
                sts32(p1 + 1024, c[dd][nt][3]);
            }
        }
    }
}

__global__ void __launch_bounds__(NTHREADS, 2)
aligned_linear_pipe(const __grid_constant__ CUtensorMap tmx,
                    const __grid_constant__ CUtensorMap tmy,
                    int ntiles)
{
    extern __shared__ uint32_t dyn[];
    const uint32_t raw   = (uint32_t)__cvta_generic_to_shared(dyn);
    const uint32_t base0 = (raw + 1023u) & ~1023u;     // SW128: 1KB align
    const uint32_t base1 = base0 + TILE_BYTES;
    const uint32_t bar0  = base1 + TILE_BYTES;
    const uint32_t bar1  = bar0 + 8;

    const int tid  = threadIdx.x;
    const int lane = tid & 31;
    const int warp = tid >> 5;
    const int g    = lane >> 2;
    const int tg   = lane & 3;

    if (tid == 0) {
        asm volatile("mbarrier.init.shared.b64 [%0], 1;" :: "r"(bar0));
        asm volatile("mbarrier.init.shared.b64 [%0], 1;" :: "r"(bar1));
    }
    __syncthreads();

    const int stride = gridDim.x;
    int tile = blockIdx.x;

    // Prologue: load first tile into buf0.
    if (tid == 0 && tile < ntiles) {
        asm volatile("mbarrier.arrive.expect_tx.shared.b64 _, [%0], %1;"
                     :: "r"(bar0), "r"(TILE_BYTES));
        asm volatile(
            "cp.async.bulk.tensor.3d.shared::cta.global.tile"
            ".mbarrier::complete_tx::bytes [%0], [%1, {%2, %3, %4}], [%5];"
            :: "r"(base0), "l"(&tmx),
               "r"(0), "r"(tile * MT), "r"(0), "r"(bar0) : "memory");
    }

    int p = 0;
    int phase0 = 0, phase1 = 0;

    for (; tile < ntiles; tile += stride, p ^= 1) {
        const uint32_t tb  = p ? base1 : base0;
        const uint32_t qb  = p ? base0 : base1;
        const uint32_t brp = p ? bar1 : bar0;
        const uint32_t brq = p ? bar0 : bar1;

        // Wait for this tile's data.
        int& ph = p ? phase1 : phase0;
        mbar_wait(brp, (uint32_t)ph);
        ph ^= 1;

        process_group<0, 0, 1>(tb, g, tg, lane, warp);
        process_group<1, 1, 3>(tb, g, tg, lane, warp);

        // Mid-compute: prefetch next tile into the other buffer. Its prior
        // store (issued one iteration ago) must drain first.
        const int tnext = tile + stride;
        if (tid == 0 && tnext < ntiles) {
            asm volatile("cp.async.bulk.wait_group 0;" ::: "memory");
            asm volatile("mbarrier.arrive.expect_tx.shared.b64 _, [%0], %1;"
                         :: "r"(brq), "r"(TILE_BYTES));
            asm volatile(
                "cp.async.bulk.tensor.3d.shared::cta.global.tile"
                ".mbarrier::complete_tx::bytes [%0], [%1, {%2, %3, %4}], [%5];"
                :: "r"(qb), "l"(&tmx),
                   "r"(0), "r"(tnext * MT), "r"(0), "r"(brq) : "memory");
        }

        process_group<2, 4, 3>(tb, g, tg, lane, warp);
        process_group<2, 7, 2>(tb, g, tg, lane, warp);

        __syncthreads();   // all writebacks into tb visible

        if (tid == 0) {
            asm volatile("fence.proxy.async;" ::: "memory");
            asm volatile(
                "cp.async.bulk.tensor.3d.global.shared::cta.tile.bulk_group "
                "[%0, {%1, %2, %3}], [%4];"
                :: "l"(&tmy), "r"(0), "r"(tile * MT), "r"(0), "r"(tb)
                : "memory");
            asm volatile("cp.async.bulk.commit_group;");
        }
    }

    if (tid == 0)
        asm volatile("cp.async.bulk.wait_group 0;" ::: "memory");
}

extern "C" void kernel_launch(void* const* d_in, const int* in_sizes, int n_in,
                              void* d_out, int out_size)
{
    const float* x = (const float*)d_in[0];
    const float* k = (const float*)d_in[1];
    float* y = (float*)d_out;
    int n_nodes = in_sizes[0] / ROWF;
    int ntiles  = (n_nodes + MT - 1) / MT;

    prep_k_kernel<<<(KB_WORDS + 255) / 256, 256>>>(k);

    typedef CUresult (*enc_t)(CUtensorMap*, CUtensorMapDataType, cuuint32_t,
                              void*, const cuuint64_t*, const cuuint64_t*,
                              const cuuint32_t*, const cuuint32_t*,
                              CUtensorMapInterleave, CUtensorMapSwizzle,
                              CUtensorMapL2promotion, CUtensorMapFloatOOBfill);
    enc_t enc = nullptr;
    {
        void* p = nullptr;
        cudaDriverEntryPointQueryResult qr;
        cudaGetDriverEntryPointByVersion("cuTensorMapEncodeTiled", &p, 12000,
                                         cudaEnableDefault, &qr);
        enc = (enc_t)p;
    }

    // View: [32 floats][node][36 segs]; box [32, MT, 36]; SW128.
    // Loads zero-fill OOB nodes; stores clip.
    cuuint64_t dims[3]    = {32, (cuuint64_t)n_nodes, 36};
    cuuint64_t strides[2] = {(cuuint64_t)ROWF * 4, 128};
    cuuint32_t box[3]     = {32, MT, 36};
    cuuint32_t es[3]      = {1, 1, 1};

    CUtensorMap tmx, tmy;
    enc(&tmx, CU_TENSOR_MAP_DATA_TYPE_FLOAT32, 3, (void*)x,
        dims, strides, box, es,
        CU_TENSOR_MAP_INTERLEAVE_NONE, CU_TENSOR_MAP_SWIZZLE_128B,
        CU_TENSOR_MAP_L2_PROMOTION_L2_128B, CU_TENSOR_MAP_FLOAT_OOB_FILL_NONE);
    enc(&tmy, CU_TENSOR_MAP_DATA_TYPE_FLOAT32, 3, (void*)y,
        dims, strides, box, es,
        CU_TENSOR_MAP_INTERLEAVE_NONE, CU_TENSOR_MAP_SWIZZLE_128B,
        CU_TENSOR_MAP_L2_PROMOTION_L2_128B, CU_TENSOR_MAP_FLOAT_OOB_FILL_NONE);

    size_t smem = 2 * TILE_BYTES + 1024 + 32;   // 2 bufs + align + 2 mbars
    cudaFuncSetAttribute(aligned_linear_pipe,
                         cudaFuncAttributeMaxDynamicSharedMemorySize,
                         (int)smem);

    int grid = 2 * 148;
    if (grid > ntiles) grid = ntiles;
    aligned_linear_pipe<<<grid, NTHREADS, smem>>>(tmx, tmy, ntiles);
}

// round 14
// speedup vs baseline: 1.5348x; 1.1080x over previous
#include <cuda_runtime.h>
#include <cuda.h>
#include <cstdint>

// AlignedLinear: y[n, o*9+d] = alpha * sum_i x[n, i*9+d] * K[r(d), i, o]
// r(d)=0 d=0; 1 d=1..3; 2 d=4..8.
//
// R14: persistent double-buffered pipeline + warpgroup specialization.
// 296 CTAs (2/SM) x 256 threads. Each CTA: two MT=12 tile buffers (SW128
// TMA layout, view [32f][node][36seg], key=(node+4*seg)&7). WG0 (warps 0-3)
// computes d=0..3 (irreps 0,1); WG1 (warps 4-7) computes d=4..8 (irrep 2,
// split 3+2 for regs). d-word sets are disjoint -> no cross-WG sync; each WG
// uses its own named barrier between reads and writeback. Mid-tile, tid0
// drains the other buffer's store and TMA-loads the next tile into it.
// m16 pad rows 12..15: A reads discarded, writeback predicated (g<4).
// B from fragment-major tf32 global buffer (alpha folded), prefetch depth 2.

#define MT        12
#define DIMT      9
#define MUL       128
#define ROWF      1152
#define TILE_BYTES (MT * ROWF * 4)      // 55296
#define SEG_STRIDE (MT * 128)           // 1536 B per seg in smem
#define NTHREADS  256
#define ALPHA_F   0.08838834764831845f  // sqrt(1/128)

#define KB_WORDS  (3 * 16 * 16 * 64)
__device__ __align__(16) uint32_t g_kbuf[KB_WORDS];

static __device__ __forceinline__ uint32_t f2tf32(float f) {
    uint32_t u;
    asm("cvt.rna.tf32.f32 %0, %1;" : "=r"(u) : "f"(f));
    return u;
}

static __device__ __forceinline__ void mma_tf32(float c[4],
    uint32_t a0, uint32_t a1, uint32_t a2, uint32_t a3,
    uint32_t b0, uint32_t b1)
{
    asm volatile(
        "mma.sync.aligned.m16n8k8.row.col.f32.tf32.tf32.f32 "
        "{%0,%1,%2,%3}, {%4,%5,%6,%7}, {%8,%9}, {%0,%1,%2,%3};"
        : "+f"(c[0]), "+f"(c[1]), "+f"(c[2]), "+f"(c[3])
        : "r"(a0), "r"(a1), "r"(a2), "r"(a3), "r"(b0), "r"(b1));
}

// ---- Prep: K[r][i][o] fp32 -> fragment-major tf32 (RNA), alpha folded ----
__global__ void prep_k_kernel(const float* __restrict__ kern)
{
    int idx = blockIdx.x * blockDim.x + threadIdx.x;
    if (idx >= KB_WORDS) return;
    int j    = idx & 1;
    int lane = (idx >> 1) & 31;
    int nt   = (idx >> 6) & 15;
    int k8   = (idx >> 10) & 15;
    int r    = idx >> 14;
    int k = k8 * 8 + (lane & 3) + 4 * j;
    int o = nt * 8 + (lane >> 2);
    g_kbuf[idx] = f2tf32(ALPHA_F * kern[(r * MUL + k) * MUL + o]);
}

// Swizzled byte offset (relative to node-row base) of word w = 9k+d.
// chunk = seg*MT + node; key = ((node + 4*seg)&7)<<4. Rows g and g+8 share
// the key; row g+8 is +1024 B.
static __device__ __forceinline__ uint32_t swz(int w, int g) {
    uint32_t s  = (uint32_t)w >> 5;
    uint32_t ky = (((uint32_t)g + 4u * s) & 7u) << 4;
    return s * (uint32_t)SEG_STRIDE + ((((uint32_t)w & 31u) << 2) ^ ky);
}

static __device__ __forceinline__ uint32_t lds32(uint32_t a) {
    uint32_t v;
    asm volatile("ld.shared.b32 %0, [%1];" : "=r"(v) : "r"(a));
    return v;
}
static __device__ __forceinline__ void sts32(uint32_t a, float v) {
    asm volatile("st.shared.b32 [%0], %1;" :: "r"(a), "f"(v));
}

static __device__ __forceinline__ void mbar_wait(uint32_t bar, uint32_t parity) {
    asm volatile(
        "{\n\t.reg .pred P;\n\t"
        "WL_%=:\n\t"
        "mbarrier.try_wait.parity.acquire.cta.shared::cta.b64 P, [%0], %1, 0x989680;\n\t"
        "@P bra WD_%=;\n\t"
        "bra WL_%=;\n\t"
        "WD_%=:\n\t}"
        :: "r"(bar), "r"(parity) : "memory");
}

static __device__ __forceinline__ void wg_bar(int id) {
    asm volatile("bar.sync %0, 128;" :: "r"(id) : "memory");
}

// One irrep group, executed by ONE warpgroup (4 warps, wwg = warp index in
// WG). BARID is that WG's named barrier (reads-done before writeback).
template<int R, int D0, int DC, int BARID>
static __device__ __forceinline__ void process_group(
    uint32_t tbase, int g, int tg, int lane, int wwg)
{
    const uint2* kb = reinterpret_cast<const uint2*>(g_kbuf)
                    + ((size_t)R * 256 + wwg * 4) * 32 + lane;
    const uint32_t rowb = tbase + (uint32_t)g * 128u;
    const bool hi_valid = (g < MT - 8);   // node g+8 exists (rows 12..15: pad)

    float c[DC][4][4];
    #pragma unroll
    for (int dd = 0; dd < DC; ++dd)
        #pragma unroll
        for (int nt = 0; nt < 4; ++nt)
            #pragma unroll
            for (int i = 0; i < 4; ++i) c[dd][nt][i] = 0.f;

    uint2 buf[2][4];
    #pragma unroll
    for (int nt = 0; nt < 4; ++nt) buf[0][nt] = __ldg(kb + nt * 32);
    #pragma unroll
    for (int nt = 0; nt < 4; ++nt) buf[1][nt] = __ldg(kb + 512 + nt * 32);

    #pragma unroll 2
    for (int k8 = 0; k8 < 16; ++k8) {
        uint2 cur[4];
        #pragma unroll
        for (int nt = 0; nt < 4; ++nt) cur[nt] = buf[k8 & 1][nt];
        if (k8 < 14) {
            const uint2* kbn = kb + (k8 + 2) * 512;
            #pragma unroll
            for (int nt = 0; nt < 4; ++nt)
                buf[k8 & 1][nt] = __ldg(kbn + nt * 32);
        }
        #pragma unroll
        for (int dd = 0; dd < DC; ++dd) {
            const int w0 = 72 * k8 + 9 * tg + (D0 + dd);
            const uint32_t o0 = rowb + swz(w0,      g);
            const uint32_t o1 = rowb + swz(w0 + 36, g);
            uint32_t a0 = lds32(o0);
            uint32_t a1 = lds32(o0 + 1024);   // pad rows: garbage, discarded
            uint32_t a2 = lds32(o1);
            uint32_t a3 = lds32(o1 + 1024);
            #pragma unroll
            for (int nt = 0; nt < 4; ++nt)
                mma_tf32(c[dd][nt], a0, a1, a2, a3, cur[nt].x, cur[nt].y);
        }
    }

    wg_bar(BARID);   // this WG done reading its d-words of this group

    #pragma unroll
    for (int dd = 0; dd < DC; ++dd) {
        #pragma unroll
        for (int nt = 0; nt < 4; ++nt) {
            const int o = wwg * 32 + nt * 8 + 2 * tg;
            const int w = o * 9 + (D0 + dd);
            const uint32_t p0 = rowb + swz(w,     g);
            const uint32_t p1 = rowb + swz(w + 9, g);
            sts32(p0, c[dd][nt][0]);
            sts32(p1, c[dd][nt][1]);
            if (hi_valid) {
                sts32(p0 + 1024, c[dd][nt][2]);
                sts32(p1 + 1024, c[dd][nt][3]);
            }
        }
    }
}

__global__ void __launch_bounds__(NTHREADS, 2)
aligned_linear_wspipe(const __grid_constant__ CUtensorMap tmx,
                      const __grid_constant__ CUtensorMap tmy,
                      int ntiles)
{
    extern __shared__ uint32_t dyn[];
    const uint32_t raw   = (uint32_t)__cvta_generic_to_shared(dyn);
    const uint32_t base0 = (raw + 1023u) & ~1023u;     // SW128: 1KB align
    const uint32_t base1 = base0 + TILE_BYTES;
    const uint32_t bar0  = base1 + TILE_BYTES;
    const uint32_t bar1  = bar0 + 8;

    const int tid  = threadIdx.x;
    const int lane = tid & 31;
    const int warp = tid >> 5;
    const int wg   = warp >> 2;        // 0: d=0..3, 1: d=4..8
    const int wwg  = warp & 3;
    const int g    = lane >> 2;
    const int tg   = lane & 3;

    if (tid == 0) {
        asm volatile("mbarrier.init.shared.b64 [%0], 1;" :: "r"(bar0));
        asm volatile("mbarrier.init.shared.b64 [%0], 1;" :: "r"(bar1));
    }
    __syncthreads();

    const int stride = gridDim.x;
    int tile = blockIdx.x;

    // Prologue: load first tile into buf0.
    if (tid == 0 && tile < ntiles) {
        asm volatile("mbarrier.arrive.expect_tx.shared.b64 _, [%0], %1;"
                     :: "r"(bar0), "r"(TILE_BYTES));
        asm volatile(
            "cp.async.bulk.tensor.3d.shared::cta.global.tile"
            ".mbarrier::complete_tx::bytes [%0], [%1, {%2, %3, %4}], [%5];"
            :: "r"(base0), "l"(&tmx),
               "r"(0), "r"(tile * MT), "r"(0), "r"(bar0) : "memory");
    }

    int p = 0;
    int phase0 = 0, phase1 = 0;

    for (; tile < ntiles; tile += stride, p ^= 1) {
        const uint32_t tb  = p ? base1 : base0;
        const uint32_t qb  = p ? base0 : base1;
        const uint32_t brp = p ? bar1 : bar0;
        const uint32_t brq = p ? bar0 : bar1;

        int& ph = p ? phase1 : phase0;
        mbar_wait(brp, (uint32_t)ph);
        ph ^= 1;

        if (wg == 0) {
            process_group<0, 0, 1, 1>(tb, g, tg, lane, wwg);
            process_group<1, 1, 3, 1>(tb, g, tg, lane, wwg);
            // Mid-tile: prefetch next tile into the other buffer (tid0 only).
            const int tnext = tile + stride;
            if (tid == 0 && tnext < ntiles) {
                asm volatile("cp.async.bulk.wait_group 0;" ::: "memory");
                asm volatile("mbarrier.arrive.expect_tx.shared.b64 _, [%0], %1;"
                             :: "r"(brq), "r"(TILE_BYTES));
                asm volatile(
                    "cp.async.bulk.tensor.3d.shared::cta.global.tile"
                    ".mbarrier::complete_tx::bytes [%0], [%1, {%2, %3, %4}], [%5];"
                    :: "r"(qb), "l"(&tmx),
                       "r"(0), "r"(tnext * MT), "r"(0), "r"(brq) : "memory");
            }
        } else {
            process_group<2, 4, 3, 2>(tb, g, tg, lane, wwg);
            process_group<2, 7, 2, 2>(tb, g, tg, lane, wwg);
        }

        __syncthreads();   // both WGs' writebacks into tb visible

        if (tid == 0) {
            asm volatile("fence.proxy.async;" ::: "memory");
            asm volatile(
                "cp.async.bulk.tensor.3d.global.shared::cta.tile.bulk_group "
                "[%0, {%1, %2, %3}], [%4];"
                :: "l"(&tmy), "r"(0), "r"(tile * MT), "r"(0), "r"(tb)
                : "memory");
            asm volatile("cp.async.bulk.commit_group;");
        }
    }

    if (tid == 0)
        asm volatile("cp.async.bulk.wait_group 0;" ::: "memory");
}

extern "C" void kernel_launch(void* const* d_in, const int* in_sizes, int n_in,
                              void* d_out, int out_size)
{
    const float* x = (const float*)d_in[0];
    const float* k = (const float*)d_in[1];
    float* y = (float*)d_out;
    int n_nodes = in_sizes[0] / ROWF;
    int ntiles  = (n_nodes + MT - 1) / MT;

    prep_k_kernel<<<(KB_WORDS + 255) / 256, 256>>>(k);

    typedef CUresult (*enc_t)(CUtensorMap*, CUtensorMapDataType, cuuint32_t,
                              void*, const cuuint64_t*, const cuuint64_t*,
                              const cuuint32_t*, const cuuint32_t*,
                              CUtensorMapInterleave, CUtensorMapSwizzle,
                              CUtensorMapL2promotion, CUtensorMapFloatOOBfill);
    enc_t enc = nullptr;
    {
        void* p = nullptr;
        cudaDriverEntryPointQueryResult qr;
        cudaGetDriverEntryPointByVersion("cuTensorMapEncodeTiled", &p, 12000,
                                         cudaEnableDefault, &qr);
        enc = (enc_t)p;
    }

    // View: [32 floats][node][36 segs]; box [32, MT, 36]; SW128.
    // Loads zero-fill OOB nodes; stores clip.
    cuuint64_t dims[3]    = {32, (cuuint64_t)n_nodes, 36};
    cuuint64_t strides[2] = {(cuuint64_t)ROWF * 4, 128};
    cuuint32_t box[3]     = {32, MT, 36};
    cuuint32_t es[3]      = {1, 1, 1};

    CUtensorMap tmx, tmy;
    enc(&tmx, CU_TENSOR_MAP_DATA_TYPE_FLOAT32, 3, (void*)x,
        dims, strides, box, es,
        CU_TENSOR_MAP_INTERLEAVE_NONE, CU_TENSOR_MAP_SWIZZLE_128B,
        CU_TENSOR_MAP_L2_PROMOTION_L2_128B, CU_TENSOR_MAP_FLOAT_OOB_FILL_NONE);
    enc(&tmy, CU_TENSOR_MAP_DATA_TYPE_FLOAT32, 3, (void*)y,
        dims, strides, box, es,
        CU_TENSOR_MAP_INTERLEAVE_NONE, CU_TENSOR_MAP_SWIZZLE_128B,
        CU_TENSOR_MAP_L2_PROMOTION_L2_128B, CU_TENSOR_MAP_FLOAT_OOB_FILL_NONE);

    size_t smem = 2 * TILE_BYTES + 1024 + 32;   // 2 bufs + align + 2 mbars
    cudaFuncSetAttribute(aligned_linear_wspipe,
                         cudaFuncAttributeMaxDynamicSharedMemorySize,
                         (int)smem);

    int grid = 2 * 148;
    if (grid > ntiles) grid = ntiles;
    aligned_linear_wspipe<<<grid, NTHREADS, smem>>>(tmx, tmy, ntiles);
}